// round 11
// baseline (speedup 1.0000x reference)
#include <cuda_runtime.h>
#include <cstdint>

#define BB 128
#define TT 256
#define HH 512
#define G4 2048  // 4*H
#define NCTA 128

// ---------------- scratch (device globals; no allocation allowed) ----------
__device__ float g_xproj[(size_t)2 * TT * BB * G4];  // [d][t][b][4H], scan order
__device__ float g_hout0[(size_t)2 * TT * BB * HH];  // layer-0 outputs [d][t][b][H]
__device__ float g_h[2][2][BB][HH];                  // [parity][d][b][h], tf32-pre-rounded
__device__ unsigned g_leaf[2][4][128];               // [d][leaf][pad512B] tree leaves
__device__ unsigned g_root[2][128];                  // [d][pad512B] tree roots

// ---------------- tf32 helpers --------------------------------------------
__device__ __forceinline__ uint32_t f2tf(float f) {
    uint32_t u;
    asm("cvt.rna.tf32.f32 %0, %1;" : "=r"(u) : "f"(f));  // round-to-nearest (unbiased)
    return u;
}

__device__ __forceinline__ void mma8(float* c, const uint32_t* a, const uint32_t* b) {
    asm volatile(
        "mma.sync.aligned.m16n8k8.row.col.f32.tf32.tf32.f32 "
        "{%0,%1,%2,%3}, {%4,%5,%6,%7}, {%8,%9}, {%0,%1,%2,%3};"
        : "+f"(c[0]), "+f"(c[1]), "+f"(c[2]), "+f"(c[3])
        : "r"(a[0]), "r"(a[1]), "r"(a[2]), "r"(a[3]), "r"(b[0]), "r"(b[1]));
}

// fast activations: MUFU-based exp; ~1e-6 rel err << tf32 noise (4e-4)
__device__ __forceinline__ float sigm(float v) { return 1.0f / (1.0f + __expf(-v)); }
__device__ __forceinline__ float ftanh(float v) {
    return 1.0f - 2.0f / (__expf(2.0f * v) + 1.0f);  // exact +-1 saturation
}

__device__ __forceinline__ uint32_t smem_u32(const void* p) {
    uint32_t a;
    asm("{ .reg .u64 t; cvta.to.shared.u64 t, %1; cvt.u32.u64 %0, t; }"
        : "=r"(a) : "l"(p));
    return a;
}

// cp.async.cg: 16B, L1-bypass (L2-coherent with __stcg writers)
__device__ __forceinline__ void cp_async16(uint32_t dst, const void* src) {
    asm volatile("cp.async.cg.shared.global [%0], [%1], 16;" ::"r"(dst), "l"(src));
}
#define CP_COMMIT() asm volatile("cp.async.commit_group;" ::: "memory")
#define CP_WAIT0() asm volatile("cp.async.wait_group 0;" ::: "memory")
#define CP_WAIT1() asm volatile("cp.async.wait_group 1;" ::: "memory")

__device__ __forceinline__ unsigned atom_add_acqrel(unsigned* p) {
    unsigned old;
    asm volatile("atom.acq_rel.gpu.global.add.u32 %0, [%1], %2;"
                 : "=r"(old) : "l"(p), "r"(1u) : "memory");
    return old;
}
__device__ __forceinline__ unsigned ld_acquire(unsigned* p) {
    unsigned v;
    asm volatile("ld.acquire.gpu.global.u32 %0, [%1];" : "=r"(v) : "l"(p)
                 : "memory");
    return v;
}

// ---------------- init: zero h (both parities) and barrier tree -------------
__global__ void init_state_kernel() {
    int idx = blockIdx.x * blockDim.x + threadIdx.x;
    if (idx < 1024) ((unsigned*)g_leaf)[idx] = 0u;
    if (idx < 256) ((unsigned*)g_root)[idx] = 0u;
    float4 z = make_float4(0.f, 0.f, 0.f, 0.f);
    if (idx < 65536) reinterpret_cast<float4*>(&g_h[0][0][0][0])[idx] = z;
}

// no-op: shifts stream launch index so ncu samples the persistent kernel
__global__ void profile_anchor_kernel() {}

// ---------------- input-projection GEMM v2 (R9, unchanged) ------------------
#define XP_SMEM (128 * 68 * 4 + 64 * 72 * 4)  // 53248 B (dynamic)

template <int LAYER>
__global__ void __launch_bounds__(256) xproj_kernel(const float* __restrict__ x,
                                                    const float* __restrict__ Wx_all,
                                                    const float* __restrict__ b_all) {
    extern __shared__ uint32_t xsm[];
    uint32_t* As = xsm;             // [128][68]
    uint32_t* Bs = xsm + 128 * 68;  // [64][72]

    const int d = blockIdx.z;
    const int n0 = blockIdx.x * 64;
    const int m0 = blockIdx.y * 128;
    const int tid = threadIdx.x;
    const int lane = tid & 31, wid = tid >> 5;
    const int wm = wid >> 1, wn = wid & 1;  // warp tile m32 x n32

    const float* Wx = Wx_all + (size_t)(LAYER * 2 + d) * HH * G4;

    float acc[2][4][4];
#pragma unroll
    for (int mt = 0; mt < 2; mt++)
#pragma unroll
        for (int nt = 0; nt < 4; nt++)
#pragma unroll
            for (int e = 0; e < 4; e++) acc[mt][nt][e] = 0.f;

    for (int k0 = 0; k0 < HH; k0 += 64) {
        __syncthreads();
#pragma unroll
        for (int w = 0; w < 8; w++) {
            int lin = w * 256 + tid;
            int row = lin >> 4;
            int kq = lin & 15;
            int rg = m0 + row;
            int tt = rg >> 7;
            int bb = rg & (BB - 1);
            const float* src;
            if (LAYER == 0) {
                int tsrc = d ? (TT - 1 - tt) : tt;
                src = x + ((size_t)bb * TT + tsrc) * HH + k0 + kq * 4;
            } else {
                src = g_hout0 + (((size_t)d * TT + tt) * BB + bb) * HH + k0 + kq * 4;
            }
            float4 v = *(const float4*)src;
            uint32_t* dst = &As[row * 68 + kq * 4];
            dst[0] = f2tf(v.x);
            dst[1] = f2tf(v.y);
            dst[2] = f2tf(v.z);
            dst[3] = f2tf(v.w);
        }
#pragma unroll
        for (int w = 0; w < 4; w++) {
            int lin = w * 256 + tid;
            int kk = lin >> 4;
            int nq = lin & 15;
            float4 v = *(const float4*)&Wx[(size_t)(k0 + kk) * G4 + n0 + nq * 4];
            uint32_t* dst = &Bs[kk * 72 + nq * 4];
            dst[0] = f2tf(v.x);
            dst[1] = f2tf(v.y);
            dst[2] = f2tf(v.z);
            dst[3] = f2tf(v.w);
        }
        __syncthreads();
#pragma unroll
        for (int ks = 0; ks < 8; ks++) {
            int ak = ks * 8 + (lane & 3);
            uint32_t af[2][4], bf[4][2];
#pragma unroll
            for (int mt = 0; mt < 2; mt++) {
                int ar = wm * 32 + mt * 16 + (lane >> 2);
                af[mt][0] = As[ar * 68 + ak];
                af[mt][1] = As[(ar + 8) * 68 + ak];
                af[mt][2] = As[ar * 68 + ak + 4];
                af[mt][3] = As[(ar + 8) * 68 + ak + 4];
            }
#pragma unroll
            for (int nt = 0; nt < 4; nt++) {
                int bn = wn * 32 + nt * 8 + (lane >> 2);
                bf[nt][0] = Bs[ak * 72 + bn];
                bf[nt][1] = Bs[(ak + 4) * 72 + bn];
            }
#pragma unroll
            for (int mt = 0; mt < 2; mt++)
#pragma unroll
                for (int nt = 0; nt < 4; nt++) mma8(acc[mt][nt], af[mt], bf[nt]);
        }
    }
    const float* bias = b_all + (size_t)(LAYER * 2 + d) * G4;
#pragma unroll
    for (int mt = 0; mt < 2; mt++)
#pragma unroll
        for (int nt = 0; nt < 4; nt++) {
            int row = m0 + wm * 32 + mt * 16 + (lane >> 2);
            int col = n0 + wn * 32 + nt * 8 + 2 * (lane & 3);
            float b0v = bias[col], b1v = bias[col + 1];
            float* dst0 = g_xproj + ((size_t)d * TT * BB + row) * G4 + col;
            *(float2*)dst0 = make_float2(acc[mt][nt][0] + b0v, acc[mt][nt][1] + b1v);
            float* dst1 = g_xproj + ((size_t)d * TT * BB + row + 8) * G4 + col;
            *(float2*)dst1 = make_float2(acc[mt][nt][2] + b0v, acc[mt][nt][3] + b1v);
        }
}

// ---------------- persistent recurrence kernel ------------------------------
// 128 CTAs (64/dir), 512 threads / 16 warps, K-split (wk 0/1) as R8/R9.
// R10: per-direction 2-level tree barrier (leaf 16-arrivals x4, root x4 ->
// ~500cyc arrival vs ~3500 single-counter REDG serialization); fast
// __expf-based activations in the tail.
#define WH_STRIDE 40
#define PAC 68
#define ABW (128 * PAC)                       // words per buffer (8704)
#define AB_OFF (512 * WH_STRIDE)              // 20480 words
#define SM_WORDS (AB_OFF + 4 * ABW)           // 55296 words = 221184 B

template <int LAYER>
__global__ void __launch_bounds__(512, 1) lstm_persist_kernel(
    const float* __restrict__ Wh_all, float* __restrict__ out) {
    extern __shared__ uint32_t smw[];
    uint32_t* WhS = smw;                      // [512][40]
    uint32_t* Ab = smw + AB_OFF;              // [4][128][68]
    float* Gs0 = (float*)(smw + AB_OFF);              // overlay buf0, [128][40]
    float* Gs1 = (float*)(smw + AB_OFF + ABW);        // overlay buf1, [128][40]
    const uint32_t sbase = smem_u32(smw);

    const int tid = threadIdx.x;
    const int lane = tid & 31, wid = tid >> 5;
    const int wk = wid >> 3;          // K-half (0: k<256, 1: k>=256)
    const int wt = wid & 7;           // warp tile
    const int wm = wt >> 1, wn = wt & 1;
    const int d = blockIdx.x >> 6;
    const int h0 = (blockIdx.x & 63) * 8;
    const int leaf = (blockIdx.x & 63) >> 4;  // 4 leaves x 16 CTAs

    const float* Wh = Wh_all + (size_t)(LAYER * 2 + d) * HH * G4;
    unsigned* leafc = &g_leaf[d][leaf][0];
    unsigned* rootc = &g_root[d][0];

    // ---- load Wh tile once, converted to tf32, gate strips packed n=g*8+hc
    for (int lin = tid; lin < 4096; lin += 512) {
        int k = lin >> 3;
        int q = lin & 7;
        int g = q >> 1;
        int part = (q & 1) * 4;
        float4 v = *(const float4*)&Wh[(size_t)k * G4 + g * HH + h0 + part];
        uint32_t* dst = &WhS[k * WH_STRIDE + g * 8 + part];
        dst[0] = f2tf(v.x);
        dst[1] = f2tf(v.y);
        dst[2] = f2tf(v.z);
        dst[3] = f2tf(v.w);
    }
    __syncthreads();

    const int phc = tid & 7;
    float c_reg[2] = {0.f, 0.f};

    for (int t = 0; t < TT; t++) {
        const float* hprev = &g_h[t & 1][d][0][0];
        const size_t xbase = ((size_t)d * TT * BB + (size_t)t * BB) * G4;

        // ---- prefetch this step's xproj slice into 8 regs (hidden by GEMM)
        float xpv[2][4];
#pragma unroll
        for (int e = 0; e < 2; e++) {
            int row = e * 64 + (tid >> 3);
            const float* xb = g_xproj + xbase + (size_t)row * G4 + h0 + phc;
            xpv[e][0] = __ldcg(xb);
            xpv[e][1] = __ldcg(xb + HH);
            xpv[e][2] = __ldcg(xb + 2 * HH);
            xpv[e][3] = __ldcg(xb + 3 * HH);
        }

        float acc[2][2][4];
#pragma unroll
        for (int mt = 0; mt < 2; mt++)
#pragma unroll
            for (int nt = 0; nt < 2; nt++)
#pragma unroll
                for (int e = 0; e < 4; e++) acc[mt][nt][e] = 0.f;

        // ---- prologue: G0 = {chunk0->buf0, chunk4->buf1}, G1 = {1->buf2, 5->buf3}
#pragma unroll
        for (int gph = 0; gph < 2; gph++) {
#pragma unroll
            for (int half = 0; half < 2; half++) {
                int ck = gph + half * 4;
                int bufi = gph * 2 + half;
#pragma unroll
                for (int w = 0; w < 4; w++) {
                    int p = w * 512 + tid;
                    int row = p >> 4, kq = p & 15;
                    uint32_t dst =
                        sbase + (AB_OFF + bufi * ABW + row * PAC + kq * 4) * 4;
                    cp_async16(dst, &hprev[(size_t)row * HH + ck * 64 + kq * 4]);
                }
            }
            CP_COMMIT();
        }

        // ---- 4 phases; phase p: wk0 computes chunk p, wk1 computes chunk p+4
#pragma unroll
        for (int p = 0; p < 4; p++) {
            if (p < 3) { CP_WAIT1(); } else { CP_WAIT0(); }
            __syncthreads();
            const uint32_t* Ac = &Ab[(((2 * p) & 3) + wk) * ABW];
            const int kb = wk * 256 + p * 64;
#pragma unroll
            for (int ks = 0; ks < 8; ks++) {
                uint32_t af[2][4], bfr[2][2];
                int ak = ks * 8 + (lane & 3);
                int ar = wm * 32 + (lane >> 2);
                af[0][0] = Ac[ar * PAC + ak];
                af[0][1] = Ac[(ar + 8) * PAC + ak];
                af[0][2] = Ac[ar * PAC + ak + 4];
                af[0][3] = Ac[(ar + 8) * PAC + ak + 4];
                af[1][0] = Ac[(ar + 16) * PAC + ak];
                af[1][1] = Ac[(ar + 24) * PAC + ak];
                af[1][2] = Ac[(ar + 16) * PAC + ak + 4];
                af[1][3] = Ac[(ar + 24) * PAC + ak + 4];
                int bk = kb + ks * 8 + (lane & 3);
                int bn = wn * 16 + (lane >> 2);
                bfr[0][0] = WhS[bk * WH_STRIDE + bn];
                bfr[0][1] = WhS[(bk + 4) * WH_STRIDE + bn];
                bfr[1][0] = WhS[bk * WH_STRIDE + bn + 8];
                bfr[1][1] = WhS[(bk + 4) * WH_STRIDE + bn + 8];
                mma8(acc[0][0], af[0], bfr[0]);
                mma8(acc[0][1], af[0], bfr[1]);
                mma8(acc[1][0], af[1], bfr[0]);
                mma8(acc[1][1], af[1], bfr[1]);
            }
            __syncthreads();
            if (p < 2) {
                int b0 = (2 * p) & 3;
#pragma unroll
                for (int half = 0; half < 2; half++) {
                    int ck = (p + 2) + half * 4;
#pragma unroll
                    for (int w = 0; w < 4; w++) {
                        int q = w * 512 + tid;
                        int row = q >> 4, kq = q & 15;
                        uint32_t dst =
                            sbase +
                            (AB_OFF + (b0 + half) * ABW + row * PAC + kq * 4) * 4;
                        cp_async16(dst,
                                   &hprev[(size_t)row * HH + ck * 64 + kq * 4]);
                    }
                }
                CP_COMMIT();
            }
        }

        // ---- stage partial accs (buf0/buf1 free: phase 3 read buf2/buf3)
        float* Gsw = wk ? Gs1 : Gs0;
#pragma unroll
        for (int mt = 0; mt < 2; mt++)
#pragma unroll
            for (int nt = 0; nt < 2; nt++) {
                int row = wm * 32 + mt * 16 + (lane >> 2);
                int col = wn * 16 + nt * 8 + 2 * (lane & 3);
                Gsw[row * 40 + col] = acc[mt][nt][0];
                Gsw[row * 40 + col + 1] = acc[mt][nt][1];
                Gsw[(row + 8) * 40 + col] = acc[mt][nt][2];
                Gsw[(row + 8) * 40 + col + 1] = acc[mt][nt][3];
            }
        __syncthreads();

        // ---- fused pointwise; write hnext only (inter-CTA critical path)
        float* hnext = &g_h[(t + 1) & 1][d][0][0];
        float hnv[2];
        int prow[2];
#pragma unroll
        for (int e = 0; e < 2; e++) {
            int row = e * 64 + (tid >> 3);
            prow[e] = row;
            float iv = Gs0[row * 40 + phc] + Gs1[row * 40 + phc] + xpv[e][0];
            float fv = Gs0[row * 40 + 8 + phc] + Gs1[row * 40 + 8 + phc] + xpv[e][1];
            float gv =
                Gs0[row * 40 + 16 + phc] + Gs1[row * 40 + 16 + phc] + xpv[e][2];
            float ov =
                Gs0[row * 40 + 24 + phc] + Gs1[row * 40 + 24 + phc] + xpv[e][3];
            float it = sigm(iv), ft = sigm(fv), gt = ftanh(gv), ot = sigm(ov);
            float cn = ft * c_reg[e] + it * gt;
            c_reg[e] = cn;
            float hn = ot * ftanh(cn);
            hnv[e] = hn;
            __stcg(&hnext[row * HH + h0 + phc], __uint_as_float(f2tf(hn)));
        }

        // ---- tree arrive (leaf 16 arrivals; last arriver propagates to root)
        __syncthreads();
        if (tid == 0) {
            unsigned old = atom_add_acqrel(leafc);
            if (old == 16u * (unsigned)(t + 1) - 1u) atom_add_acqrel(rootc);
        }

        // ---- output stores overlap the spin (not read by peers this step)
#pragma unroll
        for (int e = 0; e < 2; e++) {
            int row = prow[e];
            if (LAYER == 0) {
                g_hout0[(((size_t)d * TT + t) * BB + row) * HH + h0 + phc] = hnv[e];
            } else {
                int torig = d ? (TT - 1 - t) : t;
                out[((size_t)row * TT + torig) * (2 * HH) + (size_t)d * HH + h0 +
                    phc] = hnv[e];
            }
        }

        if (tid == 0) {
            unsigned target = 4u * (unsigned)(t + 1);
            while (ld_acquire(rootc) < target) {
            }
        }
        __syncthreads();
    }
}

// ---------------- launch ----------------------------------------------------
extern "C" void kernel_launch(void* const* d_in, const int* in_sizes, int n_in,
                              void* d_out, int out_size) {
    const float* x = (const float*)d_in[0];   // [B, T, H]
    const float* Wx = (const float*)d_in[1];  // [L, 2, H, 4H]
    const float* Wh = (const float*)d_in[2];  // [L, 2, H, 4H]
    const float* b = (const float*)d_in[3];   // [L, 2, 4H]
    float* out = (float*)d_out;               // [B, T, 2H]

    const int smem_bytes = SM_WORDS * 4;  // 221184
    cudaFuncSetAttribute(lstm_persist_kernel<0>,
                         cudaFuncAttributeMaxDynamicSharedMemorySize, smem_bytes);
    cudaFuncSetAttribute(lstm_persist_kernel<1>,
                         cudaFuncAttributeMaxDynamicSharedMemorySize, smem_bytes);
    cudaFuncSetAttribute(xproj_kernel<0>,
                         cudaFuncAttributeMaxDynamicSharedMemorySize, XP_SMEM);
    cudaFuncSetAttribute(xproj_kernel<1>,
                         cudaFuncAttributeMaxDynamicSharedMemorySize, XP_SMEM);

    dim3 gx(G4 / 64, (TT * BB) / 128, 2);

    // ---- layer 0 ----  (anchor keeps stream pos aligned for ncu sampling)
    xproj_kernel<0><<<gx, 256, XP_SMEM>>>(x, Wx, b);
    init_state_kernel<<<256, 256>>>();
    profile_anchor_kernel<<<1, 32>>>();
    lstm_persist_kernel<0><<<NCTA, 512, smem_bytes>>>(Wh, nullptr);

    // ---- layer 1 ----
    xproj_kernel<1><<<gx, 256, XP_SMEM>>>(x, Wx, b);
    init_state_kernel<<<256, 256>>>();
    lstm_persist_kernel<1><<<NCTA, 512, smem_bytes>>>(Wh, out);
}

// round 12
// speedup vs baseline: 1.5442x; 1.5442x over previous
#include <cuda_runtime.h>
#include <cstdint>

#define BB 128
#define TT 256
#define HH 512
#define G4 2048  // 4*H
#define NCTA 128
#define NCTA_DIR 64

// ---------------- scratch (device globals; no allocation allowed) ----------
__device__ float g_xproj[(size_t)2 * TT * BB * G4];  // [d][t][b][4H], scan order
__device__ float g_hout0[(size_t)2 * TT * BB * HH];  // layer-0 outputs [d][t][b][H]
__device__ float g_h[2][2][BB][HH];                  // [parity][d][b][h], tf32-pre-rounded
__device__ unsigned g_bars[2][128];                  // per-direction counters (512B apart)

// ---------------- tf32 helpers --------------------------------------------
__device__ __forceinline__ uint32_t f2tf(float f) {
    uint32_t u;
    asm("cvt.rna.tf32.f32 %0, %1;" : "=r"(u) : "f"(f));  // round-to-nearest (unbiased)
    return u;
}

__device__ __forceinline__ void mma8(float* c, const uint32_t* a, const uint32_t* b) {
    asm volatile(
        "mma.sync.aligned.m16n8k8.row.col.f32.tf32.tf32.f32 "
        "{%0,%1,%2,%3}, {%4,%5,%6,%7}, {%8,%9}, {%0,%1,%2,%3};"
        : "+f"(c[0]), "+f"(c[1]), "+f"(c[2]), "+f"(c[3])
        : "r"(a[0]), "r"(a[1]), "r"(a[2]), "r"(a[3]), "r"(b[0]), "r"(b[1]));
}

// fast activations: MUFU-based exp; ~1e-6 rel err << tf32 noise (4e-4)
__device__ __forceinline__ float sigm(float v) { return 1.0f / (1.0f + __expf(-v)); }
__device__ __forceinline__ float ftanh(float v) {
    return 1.0f - 2.0f / (__expf(2.0f * v) + 1.0f);  // exact +-1 saturation
}

__device__ __forceinline__ uint32_t smem_u32(const void* p) {
    uint32_t a;
    asm("{ .reg .u64 t; cvta.to.shared.u64 t, %1; cvt.u32.u64 %0, t; }"
        : "=r"(a) : "l"(p));
    return a;
}

// cp.async.cg: 16B, L1-bypass (L2-coherent with __stcg writers)
__device__ __forceinline__ void cp_async16(uint32_t dst, const void* src) {
    asm volatile("cp.async.cg.shared.global [%0], [%1], 16;" ::"r"(dst), "l"(src));
}
#define CP_COMMIT() asm volatile("cp.async.commit_group;" ::: "memory")
#define CP_WAIT0() asm volatile("cp.async.wait_group 0;" ::: "memory")
#define CP_WAIT1() asm volatile("cp.async.wait_group 1;" ::: "memory")

__device__ __forceinline__ void bar_arrive_release(unsigned* ctr) {
    asm volatile("red.release.gpu.global.add.u32 [%0], %1;" ::"l"(ctr), "r"(1u)
                 : "memory");
}
__device__ __forceinline__ unsigned bar_poll_acquire(unsigned* ctr) {
    unsigned v;
    asm volatile("ld.acquire.gpu.global.u32 %0, [%1];" : "=r"(v) : "l"(ctr)
                 : "memory");
    return v;
}

// ---------------- init: zero h (both parities) and barriers -----------------
__global__ void init_state_kernel() {
    int idx = blockIdx.x * blockDim.x + threadIdx.x;
    if (idx < 256) ((unsigned*)g_bars)[idx] = 0u;
    float4 z = make_float4(0.f, 0.f, 0.f, 0.f);
    if (idx < 65536) reinterpret_cast<float4*>(&g_h[0][0][0][0])[idx] = z;
}

// no-op: shifts stream launch index so ncu samples the persistent kernel
__global__ void profile_anchor_kernel() {}

// ---------------- input-projection GEMM v2 (R9, unchanged) ------------------
#define XP_SMEM (128 * 68 * 4 + 64 * 72 * 4)  // 53248 B (dynamic)

template <int LAYER>
__global__ void __launch_bounds__(256) xproj_kernel(const float* __restrict__ x,
                                                    const float* __restrict__ Wx_all,
                                                    const float* __restrict__ b_all) {
    extern __shared__ uint32_t xsm[];
    uint32_t* As = xsm;             // [128][68]
    uint32_t* Bs = xsm + 128 * 68;  // [64][72]

    const int d = blockIdx.z;
    const int n0 = blockIdx.x * 64;
    const int m0 = blockIdx.y * 128;
    const int tid = threadIdx.x;
    const int lane = tid & 31, wid = tid >> 5;
    const int wm = wid >> 1, wn = wid & 1;  // warp tile m32 x n32

    const float* Wx = Wx_all + (size_t)(LAYER * 2 + d) * HH * G4;

    float acc[2][4][4];
#pragma unroll
    for (int mt = 0; mt < 2; mt++)
#pragma unroll
        for (int nt = 0; nt < 4; nt++)
#pragma unroll
            for (int e = 0; e < 4; e++) acc[mt][nt][e] = 0.f;

    for (int k0 = 0; k0 < HH; k0 += 64) {
        __syncthreads();
#pragma unroll
        for (int w = 0; w < 8; w++) {
            int lin = w * 256 + tid;
            int row = lin >> 4;
            int kq = lin & 15;
            int rg = m0 + row;
            int tt = rg >> 7;
            int bb = rg & (BB - 1);
            const float* src;
            if (LAYER == 0) {
                int tsrc = d ? (TT - 1 - tt) : tt;
                src = x + ((size_t)bb * TT + tsrc) * HH + k0 + kq * 4;
            } else {
                src = g_hout0 + (((size_t)d * TT + tt) * BB + bb) * HH + k0 + kq * 4;
            }
            float4 v = *(const float4*)src;
            uint32_t* dst = &As[row * 68 + kq * 4];
            dst[0] = f2tf(v.x);
            dst[1] = f2tf(v.y);
            dst[2] = f2tf(v.z);
            dst[3] = f2tf(v.w);
        }
#pragma unroll
        for (int w = 0; w < 4; w++) {
            int lin = w * 256 + tid;
            int kk = lin >> 4;
            int nq = lin & 15;
            float4 v = *(const float4*)&Wx[(size_t)(k0 + kk) * G4 + n0 + nq * 4];
            uint32_t* dst = &Bs[kk * 72 + nq * 4];
            dst[0] = f2tf(v.x);
            dst[1] = f2tf(v.y);
            dst[2] = f2tf(v.z);
            dst[3] = f2tf(v.w);
        }
        __syncthreads();
#pragma unroll
        for (int ks = 0; ks < 8; ks++) {
            int ak = ks * 8 + (lane & 3);
            uint32_t af[2][4], bf[4][2];
#pragma unroll
            for (int mt = 0; mt < 2; mt++) {
                int ar = wm * 32 + mt * 16 + (lane >> 2);
                af[mt][0] = As[ar * 68 + ak];
                af[mt][1] = As[(ar + 8) * 68 + ak];
                af[mt][2] = As[ar * 68 + ak + 4];
                af[mt][3] = As[(ar + 8) * 68 + ak + 4];
            }
#pragma unroll
            for (int nt = 0; nt < 4; nt++) {
                int bn = wn * 32 + nt * 8 + (lane >> 2);
                bf[nt][0] = Bs[ak * 72 + bn];
                bf[nt][1] = Bs[(ak + 4) * 72 + bn];
            }
#pragma unroll
            for (int mt = 0; mt < 2; mt++)
#pragma unroll
                for (int nt = 0; nt < 4; nt++) mma8(acc[mt][nt], af[mt], bf[nt]);
        }
    }
    const float* bias = b_all + (size_t)(LAYER * 2 + d) * G4;
#pragma unroll
    for (int mt = 0; mt < 2; mt++)
#pragma unroll
        for (int nt = 0; nt < 4; nt++) {
            int row = m0 + wm * 32 + mt * 16 + (lane >> 2);
            int col = n0 + wn * 32 + nt * 8 + 2 * (lane & 3);
            float b0v = bias[col], b1v = bias[col + 1];
            float* dst0 = g_xproj + ((size_t)d * TT * BB + row) * G4 + col;
            *(float2*)dst0 = make_float2(acc[mt][nt][0] + b0v, acc[mt][nt][1] + b1v);
            float* dst1 = g_xproj + ((size_t)d * TT * BB + row + 8) * G4 + col;
            *(float2*)dst1 = make_float2(acc[mt][nt][2] + b0v, acc[mt][nt][3] + b1v);
        }
}

// ---------------- persistent recurrence kernel ------------------------------
// 128 CTAs (64/dir), 512 threads / 16 warps, K-split (wk 0/1) as R8/R9.
// R11 = R9 skeleton (flat red.release counter + ld.acquire spin, proven 7098)
// with (a) per-direction counters (64 arrivals, decoupled jitter; directions
// never read each other's g_h within a layer) and (b) fast __expf activations.
#define WH_STRIDE 40
#define PAC 68
#define ABW (128 * PAC)                       // words per buffer (8704)
#define AB_OFF (512 * WH_STRIDE)              // 20480 words
#define SM_WORDS (AB_OFF + 4 * ABW)           // 55296 words = 221184 B

template <int LAYER>
__global__ void __launch_bounds__(512, 1) lstm_persist_kernel(
    const float* __restrict__ Wh_all, float* __restrict__ out) {
    extern __shared__ uint32_t smw[];
    uint32_t* WhS = smw;                      // [512][40]
    uint32_t* Ab = smw + AB_OFF;              // [4][128][68]
    float* Gs0 = (float*)(smw + AB_OFF);              // overlay buf0, [128][40]
    float* Gs1 = (float*)(smw + AB_OFF + ABW);        // overlay buf1, [128][40]
    const uint32_t sbase = smem_u32(smw);

    const int tid = threadIdx.x;
    const int lane = tid & 31, wid = tid >> 5;
    const int wk = wid >> 3;          // K-half (0: k<256, 1: k>=256)
    const int wt = wid & 7;           // warp tile
    const int wm = wt >> 1, wn = wt & 1;
    const int d = blockIdx.x >> 6;
    const int h0 = (blockIdx.x & 63) * 8;

    const float* Wh = Wh_all + (size_t)(LAYER * 2 + d) * HH * G4;
    unsigned* ctr = &g_bars[d][0];

    // ---- load Wh tile once, converted to tf32, gate strips packed n=g*8+hc
    for (int lin = tid; lin < 4096; lin += 512) {
        int k = lin >> 3;
        int q = lin & 7;
        int g = q >> 1;
        int part = (q & 1) * 4;
        float4 v = *(const float4*)&Wh[(size_t)k * G4 + g * HH + h0 + part];
        uint32_t* dst = &WhS[k * WH_STRIDE + g * 8 + part];
        dst[0] = f2tf(v.x);
        dst[1] = f2tf(v.y);
        dst[2] = f2tf(v.z);
        dst[3] = f2tf(v.w);
    }
    __syncthreads();

    const int phc = tid & 7;
    float c_reg[2] = {0.f, 0.f};

    for (int t = 0; t < TT; t++) {
        const float* hprev = &g_h[t & 1][d][0][0];
        const size_t xbase = ((size_t)d * TT * BB + (size_t)t * BB) * G4;

        // ---- prefetch this step's xproj slice into 8 regs (hidden by GEMM)
        float xpv[2][4];
#pragma unroll
        for (int e = 0; e < 2; e++) {
            int row = e * 64 + (tid >> 3);
            const float* xb = g_xproj + xbase + (size_t)row * G4 + h0 + phc;
            xpv[e][0] = __ldcg(xb);
            xpv[e][1] = __ldcg(xb + HH);
            xpv[e][2] = __ldcg(xb + 2 * HH);
            xpv[e][3] = __ldcg(xb + 3 * HH);
        }

        float acc[2][2][4];
#pragma unroll
        for (int mt = 0; mt < 2; mt++)
#pragma unroll
            for (int nt = 0; nt < 2; nt++)
#pragma unroll
                for (int e = 0; e < 4; e++) acc[mt][nt][e] = 0.f;

        // ---- prologue: G0 = {chunk0->buf0, chunk4->buf1}, G1 = {1->buf2, 5->buf3}
#pragma unroll
        for (int gph = 0; gph < 2; gph++) {
#pragma unroll
            for (int half = 0; half < 2; half++) {
                int ck = gph + half * 4;
                int bufi = gph * 2 + half;
#pragma unroll
                for (int w = 0; w < 4; w++) {
                    int p = w * 512 + tid;
                    int row = p >> 4, kq = p & 15;
                    uint32_t dst =
                        sbase + (AB_OFF + bufi * ABW + row * PAC + kq * 4) * 4;
                    cp_async16(dst, &hprev[(size_t)row * HH + ck * 64 + kq * 4]);
                }
            }
            CP_COMMIT();
        }

        // ---- 4 phases; phase p: wk0 computes chunk p, wk1 computes chunk p+4
#pragma unroll
        for (int p = 0; p < 4; p++) {
            if (p < 3) { CP_WAIT1(); } else { CP_WAIT0(); }
            __syncthreads();
            const uint32_t* Ac = &Ab[(((2 * p) & 3) + wk) * ABW];
            const int kb = wk * 256 + p * 64;
#pragma unroll
            for (int ks = 0; ks < 8; ks++) {
                uint32_t af[2][4], bfr[2][2];
                int ak = ks * 8 + (lane & 3);
                int ar = wm * 32 + (lane >> 2);
                af[0][0] = Ac[ar * PAC + ak];
                af[0][1] = Ac[(ar + 8) * PAC + ak];
                af[0][2] = Ac[ar * PAC + ak + 4];
                af[0][3] = Ac[(ar + 8) * PAC + ak + 4];
                af[1][0] = Ac[(ar + 16) * PAC + ak];
                af[1][1] = Ac[(ar + 24) * PAC + ak];
                af[1][2] = Ac[(ar + 16) * PAC + ak + 4];
                af[1][3] = Ac[(ar + 24) * PAC + ak + 4];
                int bk = kb + ks * 8 + (lane & 3);
                int bn = wn * 16 + (lane >> 2);
                bfr[0][0] = WhS[bk * WH_STRIDE + bn];
                bfr[0][1] = WhS[(bk + 4) * WH_STRIDE + bn];
                bfr[1][0] = WhS[bk * WH_STRIDE + bn + 8];
                bfr[1][1] = WhS[(bk + 4) * WH_STRIDE + bn + 8];
                mma8(acc[0][0], af[0], bfr[0]);
                mma8(acc[0][1], af[0], bfr[1]);
                mma8(acc[1][0], af[1], bfr[0]);
                mma8(acc[1][1], af[1], bfr[1]);
            }
            __syncthreads();
            if (p < 2) {
                int b0 = (2 * p) & 3;
#pragma unroll
                for (int half = 0; half < 2; half++) {
                    int ck = (p + 2) + half * 4;
#pragma unroll
                    for (int w = 0; w < 4; w++) {
                        int q = w * 512 + tid;
                        int row = q >> 4, kq = q & 15;
                        uint32_t dst =
                            sbase +
                            (AB_OFF + (b0 + half) * ABW + row * PAC + kq * 4) * 4;
                        cp_async16(dst,
                                   &hprev[(size_t)row * HH + ck * 64 + kq * 4]);
                    }
                }
                CP_COMMIT();
            }
        }

        // ---- stage partial accs (buf0/buf1 free: phase 3 read buf2/buf3)
        float* Gsw = wk ? Gs1 : Gs0;
#pragma unroll
        for (int mt = 0; mt < 2; mt++)
#pragma unroll
            for (int nt = 0; nt < 2; nt++) {
                int row = wm * 32 + mt * 16 + (lane >> 2);
                int col = wn * 16 + nt * 8 + 2 * (lane & 3);
                Gsw[row * 40 + col] = acc[mt][nt][0];
                Gsw[row * 40 + col + 1] = acc[mt][nt][1];
                Gsw[(row + 8) * 40 + col] = acc[mt][nt][2];
                Gsw[(row + 8) * 40 + col + 1] = acc[mt][nt][3];
            }
        __syncthreads();

        // ---- fused pointwise; write hnext only (inter-CTA critical path)
        float* hnext = &g_h[(t + 1) & 1][d][0][0];
        float hnv[2];
        int prow[2];
#pragma unroll
        for (int e = 0; e < 2; e++) {
            int row = e * 64 + (tid >> 3);
            prow[e] = row;
            float iv = Gs0[row * 40 + phc] + Gs1[row * 40 + phc] + xpv[e][0];
            float fv = Gs0[row * 40 + 8 + phc] + Gs1[row * 40 + 8 + phc] + xpv[e][1];
            float gv =
                Gs0[row * 40 + 16 + phc] + Gs1[row * 40 + 16 + phc] + xpv[e][2];
            float ov =
                Gs0[row * 40 + 24 + phc] + Gs1[row * 40 + 24 + phc] + xpv[e][3];
            float it = sigm(iv), ft = sigm(fv), gt = ftanh(gv), ot = sigm(ov);
            float cn = ft * c_reg[e] + it * gt;
            c_reg[e] = cn;
            float hn = ot * ftanh(cn);
            hnv[e] = hn;
            __stcg(&hnext[row * HH + h0 + phc], __uint_as_float(f2tf(hn)));
        }

        // ---- arrive early (release covers hnext via syncthreads cumulativity)
        __syncthreads();
        if (tid == 0) bar_arrive_release(ctr);

        // ---- output stores overlap the spin (not read by peers this step)
#pragma unroll
        for (int e = 0; e < 2; e++) {
            int row = prow[e];
            if (LAYER == 0) {
                g_hout0[(((size_t)d * TT + t) * BB + row) * HH + h0 + phc] = hnv[e];
            } else {
                int torig = d ? (TT - 1 - t) : t;
                out[((size_t)row * TT + torig) * (2 * HH) + (size_t)d * HH + h0 +
                    phc] = hnv[e];
            }
        }

        if (tid == 0) {
            unsigned target = (unsigned)NCTA_DIR * (unsigned)(t + 1);
            while (bar_poll_acquire(ctr) < target) {
            }
        }
        __syncthreads();
    }
}

// ---------------- launch ----------------------------------------------------
extern "C" void kernel_launch(void* const* d_in, const int* in_sizes, int n_in,
                              void* d_out, int out_size) {
    const float* x = (const float*)d_in[0];   // [B, T, H]
    const float* Wx = (const float*)d_in[1];  // [L, 2, H, 4H]
    const float* Wh = (const float*)d_in[2];  // [L, 2, H, 4H]
    const float* b = (const float*)d_in[3];   // [L, 2, 4H]
    float* out = (float*)d_out;               // [B, T, 2H]

    const int smem_bytes = SM_WORDS * 4;  // 221184
    cudaFuncSetAttribute(lstm_persist_kernel<0>,
                         cudaFuncAttributeMaxDynamicSharedMemorySize, smem_bytes);
    cudaFuncSetAttribute(lstm_persist_kernel<1>,
                         cudaFuncAttributeMaxDynamicSharedMemorySize, smem_bytes);
    cudaFuncSetAttribute(xproj_kernel<0>,
                         cudaFuncAttributeMaxDynamicSharedMemorySize, XP_SMEM);
    cudaFuncSetAttribute(xproj_kernel<1>,
                         cudaFuncAttributeMaxDynamicSharedMemorySize, XP_SMEM);

    dim3 gx(G4 / 64, (TT * BB) / 128, 2);

    // ---- layer 0 ----  (anchor keeps stream pos aligned for ncu sampling)
    xproj_kernel<0><<<gx, 256, XP_SMEM>>>(x, Wx, b);
    init_state_kernel<<<256, 256>>>();
    profile_anchor_kernel<<<1, 32>>>();
    lstm_persist_kernel<0><<<NCTA, 512, smem_bytes>>>(Wh, nullptr);

    // ---- layer 1 ----
    xproj_kernel<1><<<gx, 256, XP_SMEM>>>(x, Wx, b);
    init_state_kernel<<<256, 256>>>();
    lstm_persist_kernel<1><<<NCTA, 512, smem_bytes>>>(Wh, out);
}